// round 13
// baseline (speedup 1.0000x reference)
#include <cuda_runtime.h>
#include <cstdint>
#include <cstddef>

#define HID 512
#define TT  1024
#define NB  128
#define RTOT (NB*TT)

// ping-pong activation buffers (xp in / ys out, in place), 256 MB each
__device__ float g_bufA[(size_t)RTOT * HID];
__device__ float g_bufB[(size_t)RTOT * HID];

// ---------------- helpers ----------------
__device__ __forceinline__ uint32_t smem_u32(const void* p) {
    return (uint32_t)__cvta_generic_to_shared(p);
}
__device__ __forceinline__ uint32_t mapa_u32(uint32_t addr, uint32_t rank) {
    uint32_t r;
    asm("mapa.shared::cluster.u32 %0, %1, %2;" : "=r"(r) : "r"(addr), "r"(rank));
    return r;
}
__device__ __forceinline__ void st_cluster_f32(uint32_t addr, float v) {
    asm volatile("st.shared::cluster.f32 [%0], %1;" :: "r"(addr), "f"(v) : "memory");
}
__device__ __forceinline__ void cluster_sync_all() {
    asm volatile("barrier.cluster.arrive.aligned;" ::: "memory");
    asm volatile("barrier.cluster.wait.aligned;" ::: "memory");
}
__device__ __forceinline__ uint32_t ctarank() {
    uint32_t r; asm("mov.u32 %0, %%cluster_ctarank;" : "=r"(r)); return r;
}
__device__ __forceinline__ void mbar_init(uint32_t addr, uint32_t cnt) {
    asm volatile("mbarrier.init.shared.b64 [%0], %1;" :: "r"(addr), "r"(cnt) : "memory");
}
__device__ __forceinline__ void mbar_arrive_remote(uint32_t local_addr, uint32_t rank) {
    uint32_t ra = mapa_u32(local_addr, rank);
    asm volatile("mbarrier.arrive.release.cluster.shared::cluster.b64 _, [%0];"
                 :: "r"(ra) : "memory");
}
__device__ __forceinline__ void mbar_wait(uint32_t addr, uint32_t parity) {
    asm volatile(
        "{\n\t.reg .pred P;\n"
        "WAIT_%=:\n\t"
        "mbarrier.try_wait.parity.acquire.cluster.shared::cta.b64 P, [%0], %1, 0x989680;\n\t"
        "@!P bra WAIT_%=;\n\t}"
        :: "r"(addr), "r"(parity) : "memory");
}
// accurate tanh, immune to --use_fast_math's tanh.approx
__device__ __forceinline__ float my_tanh(float x) {
    float e = __expf(2.0f * x);
    return 1.0f - 2.0f / (e + 1.0f);
}
// butterfly-merge: keep the half matching this lane's bit, add partner's other half
__device__ __forceinline__ float bfly_merge(float lo, float hi, unsigned bit, int mask) {
    float keep = bit ? hi : lo;
    float send = bit ? lo : hi;
    return keep + __shfl_xor_sync(0xffffffffu, send, mask);
}

// ---------------- xp0: (B*T,24) @ W_ih0^T -> (B*T,512) + bias ----------------
__global__ __launch_bounds__(256) void xp0_kernel(
    const float* __restrict__ x, const float* __restrict__ Wih,
    const float* __restrict__ bi, const float* __restrict__ bh,
    float* __restrict__ out)
{
    __shared__ float xs[32 * 24];
    int tid = threadIdx.x;
    int r0 = blockIdx.x * 32;
    int h0 = tid * 2;

    float w0[24], w1[24];
    const float4* wp0 = (const float4*)(Wih + (size_t)h0 * 24);
    #pragma unroll
    for (int i = 0; i < 6; i++) {
        float4 v = wp0[i];
        w0[4*i] = v.x; w0[4*i+1] = v.y; w0[4*i+2] = v.z; w0[4*i+3] = v.w;
    }
    const float4* wp1 = (const float4*)(Wih + (size_t)(h0 + 1) * 24);
    #pragma unroll
    for (int i = 0; i < 6; i++) {
        float4 v = wp1[i];
        w1[4*i] = v.x; w1[4*i+1] = v.y; w1[4*i+2] = v.z; w1[4*i+3] = v.w;
    }
    float bias0 = bi[h0] + bh[h0];
    float bias1 = bi[h0 + 1] + bh[h0 + 1];

    for (int i = tid; i < 32 * 24; i += 256) xs[i] = x[(size_t)r0 * 24 + i];
    __syncthreads();

    #pragma unroll 4
    for (int rr = 0; rr < 32; rr++) {
        float a0 = bias0, a1 = bias1;
        #pragma unroll
        for (int f = 0; f < 24; f++) {
            float xv = xs[rr * 24 + f];
            a0 = fmaf(w0[f], xv, a0);
            a1 = fmaf(w1[f], xv, a1);
        }
        *(float2*)(out + (size_t)(r0 + rr) * HID + h0) = make_float2(a0, a1);
    }
}

// ---------------- SGEMM: C[r][j] = bias[j] + sum_k A[r][k]*W[j][k] ----------------
#define GBM 128
#define GBN 128
#define GBK 16
__global__ __launch_bounds__(256, 2) void sgemm_kernel(
    const float* __restrict__ A, const float* __restrict__ W,
    const float* __restrict__ bi, const float* __restrict__ bh,
    float* __restrict__ C)
{
    __shared__ __align__(16) float As[2][GBK][GBM + 4];
    __shared__ __align__(16) float Ws[2][GBK][GBN + 4];

    int tid = threadIdx.x;
    int r0 = blockIdx.y * GBM;
    int j0 = blockIdx.x * GBN;
    int tx = tid & 15, ty = tid >> 4;

    float4 ra[2], rw[2];
    float acc[8][8];
    #pragma unroll
    for (int j = 0; j < 8; j++) {
        int jj = j0 + tx * 8 + j;
        float bj = bi[jj] + bh[jj];
        #pragma unroll
        for (int i = 0; i < 8; i++) acc[i][j] = bj;
    }

    #pragma unroll
    for (int l = 0; l < 2; l++) {
        int idx = tid + l * 256;
        int r = idx >> 2, kq = idx & 3;
        ra[l] = *(const float4*)(A + (size_t)(r0 + r) * HID + kq * 4);
        rw[l] = *(const float4*)(W + (size_t)(j0 + r) * HID + kq * 4);
    }
    #pragma unroll
    for (int l = 0; l < 2; l++) {
        int idx = tid + l * 256;
        int r = idx >> 2, kq = idx & 3;
        As[0][kq*4+0][r] = ra[l].x; As[0][kq*4+1][r] = ra[l].y;
        As[0][kq*4+2][r] = ra[l].z; As[0][kq*4+3][r] = ra[l].w;
        Ws[0][kq*4+0][r] = rw[l].x; Ws[0][kq*4+1][r] = rw[l].y;
        Ws[0][kq*4+2][r] = rw[l].z; Ws[0][kq*4+3][r] = rw[l].w;
    }
    __syncthreads();

    for (int kt = 0; kt < HID / GBK; kt++) {
        int buf = kt & 1;
        if (kt + 1 < HID / GBK) {
            int kbase = (kt + 1) * GBK;
            #pragma unroll
            for (int l = 0; l < 2; l++) {
                int idx = tid + l * 256;
                int r = idx >> 2, kq = idx & 3;
                ra[l] = *(const float4*)(A + (size_t)(r0 + r) * HID + kbase + kq * 4);
                rw[l] = *(const float4*)(W + (size_t)(j0 + r) * HID + kbase + kq * 4);
            }
        }
        #pragma unroll
        for (int k = 0; k < GBK; k++) {
            float4 a0 = *(const float4*)&As[buf][k][ty * 8];
            float4 a1 = *(const float4*)&As[buf][k][ty * 8 + 4];
            float4 b0 = *(const float4*)&Ws[buf][k][tx * 8];
            float4 b1 = *(const float4*)&Ws[buf][k][tx * 8 + 4];
            float av[8] = {a0.x, a0.y, a0.z, a0.w, a1.x, a1.y, a1.z, a1.w};
            float bv[8] = {b0.x, b0.y, b0.z, b0.w, b1.x, b1.y, b1.z, b1.w};
            #pragma unroll
            for (int i = 0; i < 8; i++)
                #pragma unroll
                for (int j = 0; j < 8; j++)
                    acc[i][j] = fmaf(av[i], bv[j], acc[i][j]);
        }
        if (kt + 1 < HID / GBK) {
            int nb = buf ^ 1;
            #pragma unroll
            for (int l = 0; l < 2; l++) {
                int idx = tid + l * 256;
                int r = idx >> 2, kq = idx & 3;
                As[nb][kq*4+0][r] = ra[l].x; As[nb][kq*4+1][r] = ra[l].y;
                As[nb][kq*4+2][r] = ra[l].z; As[nb][kq*4+3][r] = ra[l].w;
                Ws[nb][kq*4+0][r] = rw[l].x; Ws[nb][kq*4+1][r] = rw[l].y;
                Ws[nb][kq*4+2][r] = rw[l].z; Ws[nb][kq*4+3][r] = rw[l].w;
            }
        }
        __syncthreads();
    }

    #pragma unroll
    for (int i = 0; i < 8; i++) {
        int row = r0 + ty * 8 + i;
        float4 o0 = make_float4(acc[i][0], acc[i][1], acc[i][2], acc[i][3]);
        float4 o1 = make_float4(acc[i][4], acc[i][5], acc[i][6], acc[i][7]);
        *(float4*)(C + (size_t)row * HID + j0 + tx * 8)     = o0;
        *(float4*)(C + (size_t)row * HID + j0 + tx * 8 + 4) = o1;
    }
}

// ---------------- recurrence: 8-CTA cluster, 1024 threads, W in SMEM ----------------
// Diagnosis R9-R12: step is latency-bound (no pipe >27% busy) with only 4
// lockstepped warps/SMSP. This version doubles warps (occ 25%->50%) by moving
// the W_hh slice to shared memory (132KB dynamic smem), freeing registers.
//   warp w (0..31): rows 4*(w&15).., batches 4*(w>>4)..  (4x4 tile)
//   lane l: k-chunks {4l, 4l+128, 4l+256, 4l+384} (lane-consecutive float4)
//   reduce: dim-ordered butterfly (masks 16,8 fold row; 4,2 fold batch; 1
//   folds k): lane bits -> r = bit3 + 2*bit4, b = bit1 + 2*bit2; even lanes
//   (bit0=0) are writers: ys STG + 8x st.shared::cluster (4B).
// Row stride 520 floats (130 float4) keeps 16B alignment, pads never read.
__global__ __launch_bounds__(1024, 1) __cluster_dims__(8, 1, 1)
void rnn_kernel(float* __restrict__ xp, const float* __restrict__ Whh, int T,
                int writeAll)
{
    extern __shared__ __align__(16) float smem[];
    // layout (float4 units): W [64 rows][130], then h [2 bufs][8 batches][130]
    const int W4   = 64 * 130;          // 8320 float4
    const int HROW = 130;               // float4 per h row
    float4* sw = (float4*)smem;
    float4* sh = (float4*)smem + W4;

    __shared__ __align__(8) unsigned long long mbars[2];

    int tid = threadIdx.x;
    int w = tid >> 5, l = tid & 31;
    uint32_t crank = ctarank();
    int b0 = (blockIdx.x >> 3) * 8;

    int rgrp = (w & 15) * 4;            // warp's row base (local 0..63)
    int bgrp = (w >> 4) * 4;            // warp's batch base (0 or 4)

    unsigned bit4 = (l >> 4) & 1, bit3 = (l >> 3) & 1;
    unsigned bit2 = (l >> 2) & 1, bit1 = (l >> 1) & 1;
    int rout = (int)(bit3 + 2 * bit4);          // row within warp tile
    int bout = (int)(bit1 + 2 * bit2);          // batch within warp tile
    int rloc = rgrp + rout;                      // local row 0..63
    int jg   = (int)crank * 64 + rloc;           // global h row
    int bglob = b0 + bgrp + bout;                // global batch
    bool writer = (l & 1) == 0;

    uint32_t mb0 = smem_u32(&mbars[0]);
    uint32_t mb1 = smem_u32(&mbars[1]);
    if (tid == 0) { mbar_init(mb0, 8); mbar_init(mb1, 8); }

    // load W slice into smem (rows crank*64 .. +64), coalesced
    {
        const float4* wg = (const float4*)(Whh + (size_t)crank * 64 * HID);
        #pragma unroll
        for (int j = 0; j < 8; j++) {
            int f = tid + 1024 * j;          // 0..8191
            int row = f >> 7, q = f & 127;
            sw[row * 130 + q] = wg[row * 128 + q];
        }
    }
    // h_{-1} = 0 (both buffers incl. pad)
    for (int i = tid; i < 2 * 8 * HROW; i += 1024)
        sh[i] = make_float4(0.f, 0.f, 0.f, 0.f);
    __syncthreads();
    cluster_sync_all();   // mbarriers + W + zeroed h visible cluster-wide

    // writer's DSMEM target: float element h[b = bgrp+bout][jg], byte addr
    uint32_t dstbase = smem_u32(sh) + (uint32_t)((bgrp + bout) * HROW) * 16u
                       + (uint32_t)jg * 4u;
    const uint32_t BUFOFF = (uint32_t)(8 * HROW) * 16u;   // one h buffer

    // xp for t=0 (writers only need it)
    float xcur = xp[((size_t)bglob * T + 0) * HID + jg];

    const float4* swr = sw + rgrp * 130 + l;            // W rows base + lane
    const float4* shb = sh + bgrp * HROW + l;           // h batch base + lane

    for (int t = 0; t < T; t++) {
        int cur = t & 1, nxt = cur ^ 1;

        if (t > 0) mbar_wait(cur ? mb1 : mb0, (uint32_t)(((t - 1) >> 1) & 1));

        int tn = (t + 1 < T) ? t + 1 : t;
        float xnext = xp[((size_t)bglob * T + tn) * HID + jg];

        const float4* hb = shb + cur * 8 * HROW;

        float acc[4][4];
        #pragma unroll
        for (int r = 0; r < 4; r++)
            #pragma unroll
            for (int b = 0; b < 4; b++) acc[r][b] = 0.0f;

        #pragma unroll
        for (int i = 0; i < 4; i++) {
            float4 hh0 = hb[0 * HROW + 32 * i];
            float4 hh1 = hb[1 * HROW + 32 * i];
            float4 hh2 = hb[2 * HROW + 32 * i];
            float4 hh3 = hb[3 * HROW + 32 * i];
            #pragma unroll
            for (int r = 0; r < 4; r++) {
                float4 ww = swr[r * 130 + 32 * i];
                acc[r][0] = fmaf(ww.x, hh0.x, acc[r][0]);
                acc[r][0] = fmaf(ww.y, hh0.y, acc[r][0]);
                acc[r][0] = fmaf(ww.z, hh0.z, acc[r][0]);
                acc[r][0] = fmaf(ww.w, hh0.w, acc[r][0]);
                acc[r][1] = fmaf(ww.x, hh1.x, acc[r][1]);
                acc[r][1] = fmaf(ww.y, hh1.y, acc[r][1]);
                acc[r][1] = fmaf(ww.z, hh1.z, acc[r][1]);
                acc[r][1] = fmaf(ww.w, hh1.w, acc[r][1]);
                acc[r][2] = fmaf(ww.x, hh2.x, acc[r][2]);
                acc[r][2] = fmaf(ww.y, hh2.y, acc[r][2]);
                acc[r][2] = fmaf(ww.z, hh2.z, acc[r][2]);
                acc[r][2] = fmaf(ww.w, hh2.w, acc[r][2]);
                acc[r][3] = fmaf(ww.x, hh3.x, acc[r][3]);
                acc[r][3] = fmaf(ww.y, hh3.y, acc[r][3]);
                acc[r][3] = fmaf(ww.z, hh3.z, acc[r][3]);
                acc[r][3] = fmaf(ww.w, hh3.w, acc[r][3]);
            }
        }

        // dim-ordered butterfly: fold rows (masks 16, 8), batches (4, 2), k (1)
        float t1[2][4];
        #pragma unroll
        for (int b = 0; b < 4; b++) {
            t1[0][b] = bfly_merge(acc[0][b], acc[2][b], bit4, 16);
            t1[1][b] = bfly_merge(acc[1][b], acc[3][b], bit4, 16);
        }
        float t2[4];
        #pragma unroll
        for (int b = 0; b < 4; b++)
            t2[b] = bfly_merge(t1[0][b], t1[1][b], bit3, 8);
        float t3[2];
        t3[0] = bfly_merge(t2[0], t2[2], bit2, 4);
        t3[1] = bfly_merge(t2[1], t2[3], bit2, 4);
        float t4 = bfly_merge(t3[0], t3[1], bit1, 2);
        t4 += __shfl_xor_sync(0xffffffffu, t4, 1);

        float hnew = 0.0f;
        if (writer) {
            hnew = my_tanh(xcur + t4);
            if (t + 1 < T) {
                uint32_t off = nxt ? BUFOFF : 0u;
                #pragma unroll
                for (int r = 0; r < 8; r++)
                    st_cluster_f32(mapa_u32(dstbase, (uint32_t)r) + off, hnew);
            }
        }

        __syncthreads();   // all cluster stores ordered before arrives

        if (t + 1 < T && tid < 8)
            mbar_arrive_remote(nxt ? mb1 : mb0, (uint32_t)tid);

        if (writer && (writeAll || t == T - 1))
            xp[((size_t)bglob * T + t) * HID + jg] = hnew;

        xcur = xnext;
    }
}

// ---------------- head: last = ys2[:,T-1,:]; silu(last@W1^T+b1)@W2^T+b2 ----------------
__global__ __launch_bounds__(256) void head_kernel(
    const float* __restrict__ ys, const float* __restrict__ W1,
    const float* __restrict__ b1, const float* __restrict__ W2,
    const float* __restrict__ b2, float* __restrict__ out)
{
    __shared__ float hrow[HID];
    __shared__ float z[1024];
    int b = blockIdx.x;
    int tid = threadIdx.x, w = tid >> 5, l = tid & 31;

    const float* src = ys + ((size_t)b * TT + (TT - 1)) * HID;
    for (int i = tid; i < HID; i += 256) hrow[i] = src[i];
    __syncthreads();

    for (int m = w; m < 1024; m += 8) {
        const float4* wr = (const float4*)(W1 + (size_t)m * HID);
        float a = 0.0f;
        #pragma unroll
        for (int i = 0; i < 4; i++) {
            float4 wv = wr[l + 32 * i];
            float4 hv = *(const float4*)&hrow[4 * (l + 32 * i)];
            a = fmaf(wv.x, hv.x, a); a = fmaf(wv.y, hv.y, a);
            a = fmaf(wv.z, hv.z, a); a = fmaf(wv.w, hv.w, a);
        }
        a += __shfl_xor_sync(0xffffffffu, a, 16);
        a += __shfl_xor_sync(0xffffffffu, a, 8);
        a += __shfl_xor_sync(0xffffffffu, a, 4);
        a += __shfl_xor_sync(0xffffffffu, a, 2);
        a += __shfl_xor_sync(0xffffffffu, a, 1);
        if (l == 0) {
            float zz = a + b1[m];
            z[m] = zz / (1.0f + __expf(-zz));   // silu
        }
    }
    __syncthreads();

    {
        const float4* wr = (const float4*)(W2 + (size_t)w * 1024);
        float a = 0.0f;
        #pragma unroll
        for (int i = 0; i < 8; i++) {
            float4 wv = wr[l + 32 * i];
            float4 zv = *(const float4*)&z[4 * (l + 32 * i)];
            a = fmaf(wv.x, zv.x, a); a = fmaf(wv.y, zv.y, a);
            a = fmaf(wv.z, zv.z, a); a = fmaf(wv.w, zv.w, a);
        }
        a += __shfl_xor_sync(0xffffffffu, a, 16);
        a += __shfl_xor_sync(0xffffffffu, a, 8);
        a += __shfl_xor_sync(0xffffffffu, a, 4);
        a += __shfl_xor_sync(0xffffffffu, a, 2);
        a += __shfl_xor_sync(0xffffffffu, a, 1);
        if (l == 0) out[b * 8 + w] = a + b2[w];
    }
}

// ---------------- launch ----------------
extern "C" void kernel_launch(void* const* d_in, const int* in_sizes, int n_in,
                              void* d_out, int out_size) {
    const float* x     = (const float*)d_in[0];
    const float* Wih0  = (const float*)d_in[1];
    const float* Whh0  = (const float*)d_in[2];
    const float* bih0  = (const float*)d_in[3];
    const float* bhh0  = (const float*)d_in[4];
    const float* Wih1  = (const float*)d_in[5];
    const float* Whh1  = (const float*)d_in[6];
    const float* bih1  = (const float*)d_in[7];
    const float* bhh1  = (const float*)d_in[8];
    const float* Wih2  = (const float*)d_in[9];
    const float* Whh2  = (const float*)d_in[10];
    const float* bih2  = (const float*)d_in[11];
    const float* bhh2  = (const float*)d_in[12];
    const float* W1    = (const float*)d_in[13];
    const float* b1    = (const float*)d_in[14];
    const float* W2    = (const float*)d_in[15];
    const float* b2    = (const float*)d_in[16];
    float* out = (float*)d_out;

    float* bufA; cudaGetSymbolAddress((void**)&bufA, g_bufA);
    float* bufB; cudaGetSymbolAddress((void**)&bufB, g_bufB);

    // dynamic smem: W (64*130 f4) + h (2*8*130 f4) = 9'  = 166,400 B
    const int RNN_SMEM = (64 * 130 + 2 * 8 * 130) * 16;
    cudaFuncSetAttribute(rnn_kernel,
                         cudaFuncAttributeMaxDynamicSharedMemorySize, RNN_SMEM);

    // layer 0: xp0 then recurrence in place
    xp0_kernel<<<RTOT / 32, 256>>>(x, Wih0, bih0, bhh0, bufA);
    rnn_kernel<<<128, 1024, RNN_SMEM>>>(bufA, Whh0, TT, 1);

    // layer 1
    sgemm_kernel<<<dim3(HID / GBN, RTOT / GBM), 256>>>(bufA, Wih1, bih1, bhh1, bufB);
    rnn_kernel<<<128, 1024, RNN_SMEM>>>(bufB, Whh1, TT, 1);

    // layer 2 (only the last timestep of ys is consumed by the head)
    sgemm_kernel<<<dim3(HID / GBN, RTOT / GBM), 256>>>(bufB, Wih2, bih2, bhh2, bufA);
    rnn_kernel<<<128, 1024, RNN_SMEM>>>(bufA, Whh2, TT, 0);

    // head
    head_kernel<<<NB, 256>>>(bufA, W1, b1, W2, b2, out);
}

// round 14
// speedup vs baseline: 1.4847x; 1.4847x over previous
#include <cuda_runtime.h>
#include <cstdint>
#include <cstddef>

#define HID 512
#define TT  1024
#define NB  128
#define RTOT (NB*TT)

// ping-pong activation buffers (xp in / ys out, in place), 256 MB each
__device__ float g_bufA[(size_t)RTOT * HID];
__device__ float g_bufB[(size_t)RTOT * HID];

// ---------------- helpers ----------------
__device__ __forceinline__ uint32_t smem_u32(const void* p) {
    return (uint32_t)__cvta_generic_to_shared(p);
}
__device__ __forceinline__ uint32_t mapa_u32(uint32_t addr, uint32_t rank) {
    uint32_t r;
    asm("mapa.shared::cluster.u32 %0, %1, %2;" : "=r"(r) : "r"(addr), "r"(rank));
    return r;
}
__device__ __forceinline__ void cluster_sync_all() {
    asm volatile("barrier.cluster.arrive.aligned;" ::: "memory");
    asm volatile("barrier.cluster.wait.aligned;" ::: "memory");
}
__device__ __forceinline__ uint32_t ctarank() {
    uint32_t r; asm("mov.u32 %0, %%cluster_ctarank;" : "=r"(r)); return r;
}
__device__ __forceinline__ void mbar_init(uint32_t addr, uint32_t cnt) {
    asm volatile("mbarrier.init.shared.b64 [%0], %1;" :: "r"(addr), "r"(cnt) : "memory");
}
// consumer-side: arrive + declare expected transaction bytes for this phase
__device__ __forceinline__ void mbar_expect(uint32_t addr, uint32_t bytes) {
    asm volatile("mbarrier.arrive.expect_tx.shared.b64 _, [%0], %1;"
                 :: "r"(addr), "r"(bytes) : "memory");
}
// async remote store with per-byte completion on the REMOTE mbarrier
__device__ __forceinline__ void st_async_f32(uint32_t daddr, float v, uint32_t mbaddr) {
    asm volatile("st.async.shared::cluster.mbarrier::complete_tx::bytes.f32 [%0], %1, [%2];"
                 :: "r"(daddr), "f"(v), "r"(mbaddr) : "memory");
}
__device__ __forceinline__ void mbar_wait(uint32_t addr, uint32_t parity) {
    asm volatile(
        "{\n\t.reg .pred P;\n"
        "WAIT_%=:\n\t"
        "mbarrier.try_wait.parity.acquire.cluster.shared::cta.b64 P, [%0], %1, 0x989680;\n\t"
        "@!P bra WAIT_%=;\n\t}"
        :: "r"(addr), "r"(parity) : "memory");
}
// accurate tanh, immune to --use_fast_math's tanh.approx
__device__ __forceinline__ float my_tanh(float x) {
    float e = __expf(2.0f * x);
    return 1.0f - 2.0f / (e + 1.0f);
}
// butterfly-merge: keep the half matching this lane's bit, add partner's other half
__device__ __forceinline__ float bfly_merge(float lo, float hi, unsigned bit, int mask) {
    float keep = bit ? hi : lo;
    float send = bit ? lo : hi;
    return keep + __shfl_xor_sync(0xffffffffu, send, mask);
}

// ---------------- xp0: (B*T,24) @ W_ih0^T -> (B*T,512) + bias ----------------
__global__ __launch_bounds__(256) void xp0_kernel(
    const float* __restrict__ x, const float* __restrict__ Wih,
    const float* __restrict__ bi, const float* __restrict__ bh,
    float* __restrict__ out)
{
    __shared__ float xs[32 * 24];
    int tid = threadIdx.x;
    int r0 = blockIdx.x * 32;
    int h0 = tid * 2;

    float w0[24], w1[24];
    const float4* wp0 = (const float4*)(Wih + (size_t)h0 * 24);
    #pragma unroll
    for (int i = 0; i < 6; i++) {
        float4 v = wp0[i];
        w0[4*i] = v.x; w0[4*i+1] = v.y; w0[4*i+2] = v.z; w0[4*i+3] = v.w;
    }
    const float4* wp1 = (const float4*)(Wih + (size_t)(h0 + 1) * 24);
    #pragma unroll
    for (int i = 0; i < 6; i++) {
        float4 v = wp1[i];
        w1[4*i] = v.x; w1[4*i+1] = v.y; w1[4*i+2] = v.z; w1[4*i+3] = v.w;
    }
    float bias0 = bi[h0] + bh[h0];
    float bias1 = bi[h0 + 1] + bh[h0 + 1];

    for (int i = tid; i < 32 * 24; i += 256) xs[i] = x[(size_t)r0 * 24 + i];
    __syncthreads();

    #pragma unroll 4
    for (int rr = 0; rr < 32; rr++) {
        float a0 = bias0, a1 = bias1;
        #pragma unroll
        for (int f = 0; f < 24; f++) {
            float xv = xs[rr * 24 + f];
            a0 = fmaf(w0[f], xv, a0);
            a1 = fmaf(w1[f], xv, a1);
        }
        *(float2*)(out + (size_t)(r0 + rr) * HID + h0) = make_float2(a0, a1);
    }
}

// ---------------- SGEMM: C[r][j] = bias[j] + sum_k A[r][k]*W[j][k] ----------------
#define GBM 128
#define GBN 128
#define GBK 16
__global__ __launch_bounds__(256, 2) void sgemm_kernel(
    const float* __restrict__ A, const float* __restrict__ W,
    const float* __restrict__ bi, const float* __restrict__ bh,
    float* __restrict__ C)
{
    __shared__ __align__(16) float As[2][GBK][GBM + 4];
    __shared__ __align__(16) float Ws[2][GBK][GBN + 4];

    int tid = threadIdx.x;
    int r0 = blockIdx.y * GBM;
    int j0 = blockIdx.x * GBN;
    int tx = tid & 15, ty = tid >> 4;

    float4 ra[2], rw[2];
    float acc[8][8];
    #pragma unroll
    for (int j = 0; j < 8; j++) {
        int jj = j0 + tx * 8 + j;
        float bj = bi[jj] + bh[jj];
        #pragma unroll
        for (int i = 0; i < 8; i++) acc[i][j] = bj;
    }

    #pragma unroll
    for (int l = 0; l < 2; l++) {
        int idx = tid + l * 256;
        int r = idx >> 2, kq = idx & 3;
        ra[l] = *(const float4*)(A + (size_t)(r0 + r) * HID + kq * 4);
        rw[l] = *(const float4*)(W + (size_t)(j0 + r) * HID + kq * 4);
    }
    #pragma unroll
    for (int l = 0; l < 2; l++) {
        int idx = tid + l * 256;
        int r = idx >> 2, kq = idx & 3;
        As[0][kq*4+0][r] = ra[l].x; As[0][kq*4+1][r] = ra[l].y;
        As[0][kq*4+2][r] = ra[l].z; As[0][kq*4+3][r] = ra[l].w;
        Ws[0][kq*4+0][r] = rw[l].x; Ws[0][kq*4+1][r] = rw[l].y;
        Ws[0][kq*4+2][r] = rw[l].z; Ws[0][kq*4+3][r] = rw[l].w;
    }
    __syncthreads();

    for (int kt = 0; kt < HID / GBK; kt++) {
        int buf = kt & 1;
        if (kt + 1 < HID / GBK) {
            int kbase = (kt + 1) * GBK;
            #pragma unroll
            for (int l = 0; l < 2; l++) {
                int idx = tid + l * 256;
                int r = idx >> 2, kq = idx & 3;
                ra[l] = *(const float4*)(A + (size_t)(r0 + r) * HID + kbase + kq * 4);
                rw[l] = *(const float4*)(W + (size_t)(j0 + r) * HID + kbase + kq * 4);
            }
        }
        #pragma unroll
        for (int k = 0; k < GBK; k++) {
            float4 a0 = *(const float4*)&As[buf][k][ty * 8];
            float4 a1 = *(const float4*)&As[buf][k][ty * 8 + 4];
            float4 b0 = *(const float4*)&Ws[buf][k][tx * 8];
            float4 b1 = *(const float4*)&Ws[buf][k][tx * 8 + 4];
            float av[8] = {a0.x, a0.y, a0.z, a0.w, a1.x, a1.y, a1.z, a1.w};
            float bv[8] = {b0.x, b0.y, b0.z, b0.w, b1.x, b1.y, b1.z, b1.w};
            #pragma unroll
            for (int i = 0; i < 8; i++)
                #pragma unroll
                for (int j = 0; j < 8; j++)
                    acc[i][j] = fmaf(av[i], bv[j], acc[i][j]);
        }
        if (kt + 1 < HID / GBK) {
            int nb = buf ^ 1;
            #pragma unroll
            for (int l = 0; l < 2; l++) {
                int idx = tid + l * 256;
                int r = idx >> 2, kq = idx & 3;
                As[nb][kq*4+0][r] = ra[l].x; As[nb][kq*4+1][r] = ra[l].y;
                As[nb][kq*4+2][r] = ra[l].z; As[nb][kq*4+3][r] = ra[l].w;
                Ws[nb][kq*4+0][r] = rw[l].x; Ws[nb][kq*4+1][r] = rw[l].y;
                Ws[nb][kq*4+2][r] = rw[l].z; Ws[nb][kq*4+3][r] = rw[l].w;
            }
        }
        __syncthreads();
    }

    #pragma unroll
    for (int i = 0; i < 8; i++) {
        int row = r0 + ty * 8 + i;
        float4 o0 = make_float4(acc[i][0], acc[i][1], acc[i][2], acc[i][3]);
        float4 o1 = make_float4(acc[i][4], acc[i][5], acc[i][6], acc[i][7]);
        *(float4*)(C + (size_t)row * HID + j0 + tx * 8)     = o0;
        *(float4*)(C + (size_t)row * HID + j0 + tx * 8 + 4) = o1;
    }
}

// ---------------- recurrence: 8-CTA cluster, async tx-counted exchange ----------------
// R9 compute structure (TM=4 x TK=16, W in 64 regs/thread, butterfly merge),
// sync rebuilt on st.async + mbarrier complete_tx:
//  - 3 h buffers + 3 mbarriers (max CTA skew is 1 step -> 3-deep removes the
//    WAR race the old release-arrive ordering prevented)
//  - each thread st.asyncs its h value to all 8 ranks; receiver's mbar counts
//    16384 bytes; NO __syncthreads / release-arrive / drain-before-signal
//  - tid0 posts arrive.expect_tx(16KB) per phase (posted provably before any
//    matching complete_tx can land)
__global__ __launch_bounds__(512, 1) __cluster_dims__(8, 1, 1)
void rnn_kernel(float* __restrict__ xp, const float* __restrict__ Whh, int T,
                int writeAll)
{
    __shared__ __align__(16) float4 hs4[3][8][128];   // [buf][batch][i*32+l]
    __shared__ __align__(8) unsigned long long mbars[3];

    int tid = threadIdx.x;
    int w = tid >> 5, l = tid & 31;
    uint32_t crank = ctarank();
    int b0 = (blockIdx.x >> 3) * 8;

    // W tile: rows crank*64 + 4w + m, k = 16l + 4i + c   (64 regs)
    float4 w4[4][4];
    #pragma unroll
    for (int m = 0; m < 4; m++) {
        const float4* wp = (const float4*)(Whh +
            (size_t)(crank * 64 + w * 4 + m) * HID + l * 16);
        #pragma unroll
        for (int i = 0; i < 4; i++) w4[m][i] = wp[i];
    }

    unsigned bit4 = (l >> 4) & 1;
    unsigned bit3 = (l >> 3) & 1;
    int bout = ((l >> 2) & 3) | ((l >> 4) << 2);   // batch this lane owns
    int jg   = (int)crank * 64 + w * 4 + (l & 3);  // row this lane owns
    int l2 = jg >> 4, i0 = (jg >> 2) & 3, c = jg & 3;
    const uint32_t BUF = (uint32_t)(8 * 128 * 16);     // 16384 B per h buffer
    uint32_t dstbase = smem_u32(&hs4[0][bout][i0 * 32 + l2]) + (uint32_t)c * 4u;

    uint32_t mbv0 = smem_u32(&mbars[0]);
    uint32_t mbv1 = smem_u32(&mbars[1]);
    uint32_t mbv2 = smem_u32(&mbars[2]);

    if (tid == 0) { mbar_init(mbv0, 1); mbar_init(mbv1, 1); mbar_init(mbv2, 1); }

    // h_{-1} = 0 (all 3 buffers)
    for (int i = tid; i < 3 * 8 * 128; i += 512)
        ((float4*)hs4)[i] = make_float4(0.f, 0.f, 0.f, 0.f);
    __syncthreads();
    if (tid == 0) {  // expects for the first phase of each mbar (pre-sync:
        mbar_expect(mbv0, 16384u);   // guaranteed before any remote st.async)
        mbar_expect(mbv1, 16384u);
        mbar_expect(mbv2, 16384u);
    }
    cluster_sync_all();   // mbarriers + zeroed state visible cluster-wide

    // xp value this thread's output needs, prefetched one step ahead
    float xcur = xp[((size_t)(b0 + bout) * T + 0) * HID + jg];

    for (int t = 0; t < T; t++) {
        int rb = t % 3;                 // read buffer / mbar
        int wb = rb + 1 == 3 ? 0 : rb + 1;   // write buffer / mbar
        uint32_t mbr = rb == 0 ? mbv0 : (rb == 1 ? mbv1 : mbv2);
        uint32_t mbw = wb == 0 ? mbv0 : (wb == 1 ? mbv1 : mbv2);

        if (t > 0) {
            // parity of this mbar's current phase (first wait of mbar i is
            // phase 0): i!=0 -> (t/3)&1 ; i==0 -> (t/3 + 1)&1
            uint32_t par = (uint32_t)((t / 3 + (rb == 0 ? 1 : 0)) & 1);
            mbar_wait(mbr, par);
            if (tid == 0) mbar_expect(mbr, 16384u);   // next phase of this mbar
        }

        // prefetch next xp (hides under the matvec)
        int tn = (t + 1 < T) ? t + 1 : t;
        float xnext = xp[((size_t)(b0 + bout) * T + tn) * HID + jg];

        // ---- matvec + progressive butterfly reduce (R9/R10 proven form) ----
        const float4* hbuf = &hs4[rb][0][0];
        float v8[8];
        #pragma unroll
        for (int pair = 0; pair < 2; pair++) {
            float a16[8];
            #pragma unroll
            for (int e = 0; e < 2; e++) {
                int bp = pair + 2 * e;
                const float4* h0 = hbuf + bp * 128 + l;
                const float4* h1 = hbuf + (bp + 4) * 128 + l;
                float p0[4] = {0.f, 0.f, 0.f, 0.f};
                float p1[4] = {0.f, 0.f, 0.f, 0.f};
                #pragma unroll
                for (int i = 0; i < 4; i++) {
                    float4 hv0 = h0[i * 32];
                    float4 hv1 = h1[i * 32];
                    #pragma unroll
                    for (int m = 0; m < 4; m++) {
                        p0[m] = fmaf(w4[m][i].x, hv0.x, p0[m]);
                        p0[m] = fmaf(w4[m][i].y, hv0.y, p0[m]);
                        p0[m] = fmaf(w4[m][i].z, hv0.z, p0[m]);
                        p0[m] = fmaf(w4[m][i].w, hv0.w, p0[m]);
                        p1[m] = fmaf(w4[m][i].x, hv1.x, p1[m]);
                        p1[m] = fmaf(w4[m][i].y, hv1.y, p1[m]);
                        p1[m] = fmaf(w4[m][i].z, hv1.z, p1[m]);
                        p1[m] = fmaf(w4[m][i].w, hv1.w, p1[m]);
                    }
                }
                #pragma unroll
                for (int m = 0; m < 4; m++)
                    a16[e * 4 + m] = bfly_merge(p0[m], p1[m], bit4, 16);
            }
            #pragma unroll
            for (int m = 0; m < 4; m++)
                v8[pair * 4 + m] = bfly_merge(a16[m], a16[4 + m], bit3, 8);
        }
        float r4[4];
        { unsigned b2 = (l >> 2) & 1;
          #pragma unroll
          for (int q = 0; q < 4; q++) r4[q] = bfly_merge(v8[q], v8[4 + q], b2, 4); }
        float r2[2];
        { unsigned b1 = (l >> 1) & 1;
          #pragma unroll
          for (int q = 0; q < 2; q++) r2[q] = bfly_merge(r4[q], r4[2 + q], b1, 2); }
        float r1 = bfly_merge(r2[0], r2[1], l & 1, 1);

        float hnew = my_tanh(xcur + r1);

        // async push to all 8 CTAs' buffer wb; completion counted by their mbar wb
        if (t + 1 < T) {
            uint32_t da = dstbase + (uint32_t)wb * BUF;
            #pragma unroll
            for (int r = 0; r < 8; r++)
                st_async_f32(mapa_u32(da, (uint32_t)r), hnew,
                             mapa_u32(mbw, (uint32_t)r));
        }

        // ys write (off the signaling path entirely now)
        if (writeAll || t == T - 1)
            xp[((size_t)(b0 + bout) * T + t) * HID + jg] = hnew;

        xcur = xnext;
    }
}

// ---------------- head: last = ys2[:,T-1,:]; silu(last@W1^T+b1)@W2^T+b2 ----------------
__global__ __launch_bounds__(256) void head_kernel(
    const float* __restrict__ ys, const float* __restrict__ W1,
    const float* __restrict__ b1, const float* __restrict__ W2,
    const float* __restrict__ b2, float* __restrict__ out)
{
    __shared__ float hrow[HID];
    __shared__ float z[1024];
    int b = blockIdx.x;
    int tid = threadIdx.x, w = tid >> 5, l = tid & 31;

    const float* src = ys + ((size_t)b * TT + (TT - 1)) * HID;
    for (int i = tid; i < HID; i += 256) hrow[i] = src[i];
    __syncthreads();

    for (int m = w; m < 1024; m += 8) {
        const float4* wr = (const float4*)(W1 + (size_t)m * HID);
        float a = 0.0f;
        #pragma unroll
        for (int i = 0; i < 4; i++) {
            float4 wv = wr[l + 32 * i];
            float4 hv = *(const float4*)&hrow[4 * (l + 32 * i)];
            a = fmaf(wv.x, hv.x, a); a = fmaf(wv.y, hv.y, a);
            a = fmaf(wv.z, hv.z, a); a = fmaf(wv.w, hv.w, a);
        }
        a += __shfl_xor_sync(0xffffffffu, a, 16);
        a += __shfl_xor_sync(0xffffffffu, a, 8);
        a += __shfl_xor_sync(0xffffffffu, a, 4);
        a += __shfl_xor_sync(0xffffffffu, a, 2);
        a += __shfl_xor_sync(0xffffffffu, a, 1);
        if (l == 0) {
            float zz = a + b1[m];
            z[m] = zz / (1.0f + __expf(-zz));   // silu
        }
    }
    __syncthreads();

    {
        const float4* wr = (const float4*)(W2 + (size_t)w * 1024);
        float a = 0.0f;
        #pragma unroll
        for (int i = 0; i < 8; i++) {
            float4 wv = wr[l + 32 * i];
            float4 zv = *(const float4*)&z[4 * (l + 32 * i)];
            a = fmaf(wv.x, zv.x, a); a = fmaf(wv.y, zv.y, a);
            a = fmaf(wv.z, zv.z, a); a = fmaf(wv.w, zv.w, a);
        }
        a += __shfl_xor_sync(0xffffffffu, a, 16);
        a += __shfl_xor_sync(0xffffffffu, a, 8);
        a += __shfl_xor_sync(0xffffffffu, a, 4);
        a += __shfl_xor_sync(0xffffffffu, a, 2);
        a += __shfl_xor_sync(0xffffffffu, a, 1);
        if (l == 0) out[b * 8 + w] = a + b2[w];
    }
}

// ---------------- launch ----------------
extern "C" void kernel_launch(void* const* d_in, const int* in_sizes, int n_in,
                              void* d_out, int out_size) {
    const float* x     = (const float*)d_in[0];
    const float* Wih0  = (const float*)d_in[1];
    const float* Whh0  = (const float*)d_in[2];
    const float* bih0  = (const float*)d_in[3];
    const float* bhh0  = (const float*)d_in[4];
    const float* Wih1  = (const float*)d_in[5];
    const float* Whh1  = (const float*)d_in[6];
    const float* bih1  = (const float*)d_in[7];
    const float* bhh1  = (const float*)d_in[8];
    const float* Wih2  = (const float*)d_in[9];
    const float* Whh2  = (const float*)d_in[10];
    const float* bih2  = (const float*)d_in[11];
    const float* bhh2  = (const float*)d_in[12];
    const float* W1    = (const float*)d_in[13];
    const float* b1    = (const float*)d_in[14];
    const float* W2    = (const float*)d_in[15];
    const float* b2    = (const float*)d_in[16];
    float* out = (float*)d_out;

    float* bufA; cudaGetSymbolAddress((void**)&bufA, g_bufA);
    float* bufB; cudaGetSymbolAddress((void**)&bufB, g_bufB);

    // layer 0: xp0 then recurrence in place
    xp0_kernel<<<RTOT / 32, 256>>>(x, Wih0, bih0, bhh0, bufA);
    rnn_kernel<<<128, 512>>>(bufA, Whh0, TT, 1);

    // layer 1
    sgemm_kernel<<<dim3(HID / GBN, RTOT / GBM), 256>>>(bufA, Wih1, bih1, bhh1, bufB);
    rnn_kernel<<<128, 512>>>(bufB, Whh1, TT, 1);

    // layer 2 (only the last timestep of ys is consumed by the head)
    sgemm_kernel<<<dim3(HID / GBN, RTOT / GBM), 256>>>(bufB, Wih2, bih2, bhh2, bufA);
    rnn_kernel<<<128, 512>>>(bufA, Whh2, TT, 0);

    // head
    head_kernel<<<NB, 256>>>(bufA, W1, b1, W2, b2, out);
}

// round 15
// speedup vs baseline: 1.4854x; 1.0005x over previous
#include <cuda_runtime.h>
#include <cstdint>
#include <cstddef>

#define HID 512
#define TT  1024
#define NB  128
#define RTOT (NB*TT)

typedef unsigned long long u64;

// ping-pong activation buffers (xp in / ys out, in place), 256 MB each
__device__ float g_bufA[(size_t)RTOT * HID];
__device__ float g_bufB[(size_t)RTOT * HID];

// ---------------- helpers ----------------
__device__ __forceinline__ uint32_t smem_u32(const void* p) {
    return (uint32_t)__cvta_generic_to_shared(p);
}
__device__ __forceinline__ uint32_t mapa_u32(uint32_t addr, uint32_t rank) {
    uint32_t r;
    asm("mapa.shared::cluster.u32 %0, %1, %2;" : "=r"(r) : "r"(addr), "r"(rank));
    return r;
}
__device__ __forceinline__ void cluster_sync_all() {
    asm volatile("barrier.cluster.arrive.aligned;" ::: "memory");
    asm volatile("barrier.cluster.wait.aligned;" ::: "memory");
}
__device__ __forceinline__ uint32_t ctarank() {
    uint32_t r; asm("mov.u32 %0, %%cluster_ctarank;" : "=r"(r)); return r;
}
__device__ __forceinline__ void mbar_init(uint32_t addr, uint32_t cnt) {
    asm volatile("mbarrier.init.shared.b64 [%0], %1;" :: "r"(addr), "r"(cnt) : "memory");
}
// consumer-side: arrive + declare expected transaction bytes for this phase
__device__ __forceinline__ void mbar_expect(uint32_t addr, uint32_t bytes) {
    asm volatile("mbarrier.arrive.expect_tx.shared.b64 _, [%0], %1;"
                 :: "r"(addr), "r"(bytes) : "memory");
}
// async remote store with per-byte completion on the REMOTE mbarrier
__device__ __forceinline__ void st_async_f32(uint32_t daddr, float v, uint32_t mbaddr) {
    asm volatile("st.async.shared::cluster.mbarrier::complete_tx::bytes.f32 [%0], %1, [%2];"
                 :: "r"(daddr), "f"(v), "r"(mbaddr) : "memory");
}
__device__ __forceinline__ void mbar_wait(uint32_t addr, uint32_t parity) {
    asm volatile(
        "{\n\t.reg .pred P;\n"
        "WAIT_%=:\n\t"
        "mbarrier.try_wait.parity.acquire.cluster.shared::cta.b64 P, [%0], %1, 0x989680;\n\t"
        "@!P bra WAIT_%=;\n\t}"
        :: "r"(addr), "r"(parity) : "memory");
}
// accurate tanh, immune to --use_fast_math's tanh.approx
__device__ __forceinline__ float my_tanh(float x) {
    float e = __expf(2.0f * x);
    return 1.0f - 2.0f / (e + 1.0f);
}
// butterfly-merge: keep the half matching this lane's bit, add partner's other half
__device__ __forceinline__ float bfly_merge(float lo, float hi, unsigned bit, int mask) {
    float keep = bit ? hi : lo;
    float send = bit ? lo : hi;
    return keep + __shfl_xor_sync(0xffffffffu, send, mask);
}
// ---- packed fp32 (Blackwell FFMA2) ----
__device__ __forceinline__ u64 ffma2(u64 a, u64 b, u64 c) {
    u64 d;
    asm("fma.rn.f32x2 %0, %1, %2, %3;" : "=l"(d) : "l"(a), "l"(b), "l"(c));
    return d;
}
__device__ __forceinline__ u64 pack2(float x, float y) {
    u64 r;
    asm("mov.b64 %0, {%1, %2};" : "=l"(r) : "f"(x), "f"(y));
    return r;
}
__device__ __forceinline__ float unpack_sum(u64 v) {
    float lo, hi;
    asm("mov.b64 {%0, %1}, %2;" : "=f"(lo), "=f"(hi) : "l"(v));
    return lo + hi;
}

// ---------------- xp0: (B*T,24) @ W_ih0^T -> (B*T,512) + bias ----------------
__global__ __launch_bounds__(256) void xp0_kernel(
    const float* __restrict__ x, const float* __restrict__ Wih,
    const float* __restrict__ bi, const float* __restrict__ bh,
    float* __restrict__ out)
{
    __shared__ float xs[32 * 24];
    int tid = threadIdx.x;
    int r0 = blockIdx.x * 32;
    int h0 = tid * 2;

    float w0[24], w1[24];
    const float4* wp0 = (const float4*)(Wih + (size_t)h0 * 24);
    #pragma unroll
    for (int i = 0; i < 6; i++) {
        float4 v = wp0[i];
        w0[4*i] = v.x; w0[4*i+1] = v.y; w0[4*i+2] = v.z; w0[4*i+3] = v.w;
    }
    const float4* wp1 = (const float4*)(Wih + (size_t)(h0 + 1) * 24);
    #pragma unroll
    for (int i = 0; i < 6; i++) {
        float4 v = wp1[i];
        w1[4*i] = v.x; w1[4*i+1] = v.y; w1[4*i+2] = v.z; w1[4*i+3] = v.w;
    }
    float bias0 = bi[h0] + bh[h0];
    float bias1 = bi[h0 + 1] + bh[h0 + 1];

    for (int i = tid; i < 32 * 24; i += 256) xs[i] = x[(size_t)r0 * 24 + i];
    __syncthreads();

    #pragma unroll 4
    for (int rr = 0; rr < 32; rr++) {
        float a0 = bias0, a1 = bias1;
        #pragma unroll
        for (int f = 0; f < 24; f++) {
            float xv = xs[rr * 24 + f];
            a0 = fmaf(w0[f], xv, a0);
            a1 = fmaf(w1[f], xv, a1);
        }
        *(float2*)(out + (size_t)(r0 + rr) * HID + h0) = make_float2(a0, a1);
    }
}

// ---------------- SGEMM: C[r][j] = bias[j] + sum_k A[r][k]*W[j][k] ----------------
#define GBM 128
#define GBN 128
#define GBK 16
__global__ __launch_bounds__(256, 2) void sgemm_kernel(
    const float* __restrict__ A, const float* __restrict__ W,
    const float* __restrict__ bi, const float* __restrict__ bh,
    float* __restrict__ C)
{
    __shared__ __align__(16) float As[2][GBK][GBM + 4];
    __shared__ __align__(16) float Ws[2][GBK][GBN + 4];

    int tid = threadIdx.x;
    int r0 = blockIdx.y * GBM;
    int j0 = blockIdx.x * GBN;
    int tx = tid & 15, ty = tid >> 4;

    float4 ra[2], rw[2];
    float acc[8][8];
    #pragma unroll
    for (int j = 0; j < 8; j++) {
        int jj = j0 + tx * 8 + j;
        float bj = bi[jj] + bh[jj];
        #pragma unroll
        for (int i = 0; i < 8; i++) acc[i][j] = bj;
    }

    #pragma unroll
    for (int l = 0; l < 2; l++) {
        int idx = tid + l * 256;
        int r = idx >> 2, kq = idx & 3;
        ra[l] = *(const float4*)(A + (size_t)(r0 + r) * HID + kq * 4);
        rw[l] = *(const float4*)(W + (size_t)(j0 + r) * HID + kq * 4);
    }
    #pragma unroll
    for (int l = 0; l < 2; l++) {
        int idx = tid + l * 256;
        int r = idx >> 2, kq = idx & 3;
        As[0][kq*4+0][r] = ra[l].x; As[0][kq*4+1][r] = ra[l].y;
        As[0][kq*4+2][r] = ra[l].z; As[0][kq*4+3][r] = ra[l].w;
        Ws[0][kq*4+0][r] = rw[l].x; Ws[0][kq*4+1][r] = rw[l].y;
        Ws[0][kq*4+2][r] = rw[l].z; Ws[0][kq*4+3][r] = rw[l].w;
    }
    __syncthreads();

    for (int kt = 0; kt < HID / GBK; kt++) {
        int buf = kt & 1;
        if (kt + 1 < HID / GBK) {
            int kbase = (kt + 1) * GBK;
            #pragma unroll
            for (int l = 0; l < 2; l++) {
                int idx = tid + l * 256;
                int r = idx >> 2, kq = idx & 3;
                ra[l] = *(const float4*)(A + (size_t)(r0 + r) * HID + kbase + kq * 4);
                rw[l] = *(const float4*)(W + (size_t)(j0 + r) * HID + kbase + kq * 4);
            }
        }
        #pragma unroll
        for (int k = 0; k < GBK; k++) {
            float4 a0 = *(const float4*)&As[buf][k][ty * 8];
            float4 a1 = *(const float4*)&As[buf][k][ty * 8 + 4];
            float4 b0 = *(const float4*)&Ws[buf][k][tx * 8];
            float4 b1 = *(const float4*)&Ws[buf][k][tx * 8 + 4];
            float av[8] = {a0.x, a0.y, a0.z, a0.w, a1.x, a1.y, a1.z, a1.w};
            float bv[8] = {b0.x, b0.y, b0.z, b0.w, b1.x, b1.y, b1.z, b1.w};
            #pragma unroll
            for (int i = 0; i < 8; i++)
                #pragma unroll
                for (int j = 0; j < 8; j++)
                    acc[i][j] = fmaf(av[i], bv[j], acc[i][j]);
        }
        if (kt + 1 < HID / GBK) {
            int nb = buf ^ 1;
            #pragma unroll
            for (int l = 0; l < 2; l++) {
                int idx = tid + l * 256;
                int r = idx >> 2, kq = idx & 3;
                As[nb][kq*4+0][r] = ra[l].x; As[nb][kq*4+1][r] = ra[l].y;
                As[nb][kq*4+2][r] = ra[l].z; As[nb][kq*4+3][r] = ra[l].w;
                Ws[nb][kq*4+0][r] = rw[l].x; Ws[nb][kq*4+1][r] = rw[l].y;
                Ws[nb][kq*4+2][r] = rw[l].z; Ws[nb][kq*4+3][r] = rw[l].w;
            }
        }
        __syncthreads();
    }

    #pragma unroll
    for (int i = 0; i < 8; i++) {
        int row = r0 + ty * 8 + i;
        float4 o0 = make_float4(acc[i][0], acc[i][1], acc[i][2], acc[i][3]);
        float4 o1 = make_float4(acc[i][4], acc[i][5], acc[i][6], acc[i][7]);
        *(float4*)(C + (size_t)row * HID + j0 + tx * 8)     = o0;
        *(float4*)(C + (size_t)row * HID + j0 + tx * 8 + 4) = o1;
    }
}

// ---------------- recurrence: R14 async exchange + FFMA2 matvec ----------------
// R14 skeleton (3 h buffers, st.async + mbarrier complete_tx, no syncthreads
// in the loop) with the matvec in Blackwell fma.rn.f32x2 form: W packed as
// f32x2 pairs (64 regs), h read as ulonglong2 (same LDS.128), (even,odd)
// partials folded with one add before the butterfly. Per-thread FMA instrs
// 512 -> 256; tests whether FFMA2 halves fma pipe-time now that the kernel
// is no longer lockstep-sync dominated.
__global__ __launch_bounds__(512, 1) __cluster_dims__(8, 1, 1)
void rnn_kernel(float* __restrict__ xp, const float* __restrict__ Whh, int T,
                int writeAll)
{
    __shared__ __align__(16) float4 hs4[3][8][128];   // [buf][batch][i*32+l]
    __shared__ __align__(8) unsigned long long mbars[3];

    int tid = threadIdx.x;
    int w = tid >> 5, l = tid & 31;
    uint32_t crank = ctarank();
    int b0 = (blockIdx.x >> 3) * 8;

    // W tile rows crank*64 + 4w + m, k = 16l + .. ; packed as f32x2 pairs
    u64 w2[4][8];
    #pragma unroll
    for (int m = 0; m < 4; m++) {
        const float4* wp = (const float4*)(Whh +
            (size_t)(crank * 64 + w * 4 + m) * HID + l * 16);
        #pragma unroll
        for (int i = 0; i < 4; i++) {
            float4 v = wp[i];
            w2[m][2*i]   = pack2(v.x, v.y);
            w2[m][2*i+1] = pack2(v.z, v.w);
        }
    }

    unsigned bit4 = (l >> 4) & 1;
    unsigned bit3 = (l >> 3) & 1;
    int bout = ((l >> 2) & 3) | ((l >> 4) << 2);   // batch this lane owns
    int jg   = (int)crank * 64 + w * 4 + (l & 3);  // row this lane owns
    int l2 = jg >> 4, i0 = (jg >> 2) & 3, c = jg & 3;
    const uint32_t BUF = (uint32_t)(8 * 128 * 16);     // 16384 B per h buffer
    uint32_t dstbase = smem_u32(&hs4[0][bout][i0 * 32 + l2]) + (uint32_t)c * 4u;

    uint32_t mbv0 = smem_u32(&mbars[0]);
    uint32_t mbv1 = smem_u32(&mbars[1]);
    uint32_t mbv2 = smem_u32(&mbars[2]);

    if (tid == 0) { mbar_init(mbv0, 1); mbar_init(mbv1, 1); mbar_init(mbv2, 1); }

    // h_{-1} = 0 (all 3 buffers)
    for (int i = tid; i < 3 * 8 * 128; i += 512)
        ((float4*)hs4)[i] = make_float4(0.f, 0.f, 0.f, 0.f);
    __syncthreads();
    if (tid == 0) {  // first-phase expects, posted before any remote st.async
        mbar_expect(mbv0, 16384u);
        mbar_expect(mbv1, 16384u);
        mbar_expect(mbv2, 16384u);
    }
    cluster_sync_all();   // mbarriers + zeroed state visible cluster-wide

    // xp value this thread's output needs, prefetched one step ahead
    float xcur = xp[((size_t)(b0 + bout) * T + 0) * HID + jg];

    for (int t = 0; t < T; t++) {
        int rb = t % 3;
        int wb = rb + 1 == 3 ? 0 : rb + 1;
        uint32_t mbr = rb == 0 ? mbv0 : (rb == 1 ? mbv1 : mbv2);
        uint32_t mbw = wb == 0 ? mbv0 : (wb == 1 ? mbv1 : mbv2);

        if (t > 0) {
            uint32_t par = (uint32_t)((t / 3 + (rb == 0 ? 1 : 0)) & 1);
            mbar_wait(mbr, par);
            if (tid == 0) mbar_expect(mbr, 16384u);
        }

        // prefetch next xp (hides under the matvec)
        int tn = (t + 1 < T) ? t + 1 : t;
        float xnext = xp[((size_t)(b0 + bout) * T + tn) * HID + jg];

        // ---- FFMA2 matvec + progressive butterfly reduce ----
        const float4* hbuf = &hs4[rb][0][0];
        float v8[8];
        #pragma unroll
        for (int pair = 0; pair < 2; pair++) {
            float a16[8];
            #pragma unroll
            for (int e = 0; e < 2; e++) {
                int bp = pair + 2 * e;
                const ulonglong2* h0 = (const ulonglong2*)(hbuf + bp * 128 + l);
                const ulonglong2* h1 = (const ulonglong2*)(hbuf + (bp + 4) * 128 + l);
                u64 p0[4], p1[4];
                #pragma unroll
                for (int m = 0; m < 4; m++) { p0[m] = 0ULL; p1[m] = 0ULL; }
                #pragma unroll
                for (int i = 0; i < 4; i++) {
                    ulonglong2 hv0 = h0[i * 32];   // (k0,k1),(k2,k3)
                    ulonglong2 hv1 = h1[i * 32];
                    #pragma unroll
                    for (int m = 0; m < 4; m++) {
                        p0[m] = ffma2(w2[m][2*i],   hv0.x, p0[m]);
                        p0[m] = ffma2(w2[m][2*i+1], hv0.y, p0[m]);
                        p1[m] = ffma2(w2[m][2*i],   hv1.x, p1[m]);
                        p1[m] = ffma2(w2[m][2*i+1], hv1.y, p1[m]);
                    }
                }
                #pragma unroll
                for (int m = 0; m < 4; m++)
                    a16[e * 4 + m] = bfly_merge(unpack_sum(p0[m]),
                                                unpack_sum(p1[m]), bit4, 16);
            }
            #pragma unroll
            for (int m = 0; m < 4; m++)
                v8[pair * 4 + m] = bfly_merge(a16[m], a16[4 + m], bit3, 8);
        }
        float r4[4];
        { unsigned b2 = (l >> 2) & 1;
          #pragma unroll
          for (int q = 0; q < 4; q++) r4[q] = bfly_merge(v8[q], v8[4 + q], b2, 4); }
        float r2[2];
        { unsigned b1 = (l >> 1) & 1;
          #pragma unroll
          for (int q = 0; q < 2; q++) r2[q] = bfly_merge(r4[q], r4[2 + q], b1, 2); }
        float r1 = bfly_merge(r2[0], r2[1], l & 1, 1);

        float hnew = my_tanh(xcur + r1);

        // async push to all 8 CTAs' buffer wb; completion counted by their mbar wb
        if (t + 1 < T) {
            uint32_t da = dstbase + (uint32_t)wb * BUF;
            #pragma unroll
            for (int r = 0; r < 8; r++)
                st_async_f32(mapa_u32(da, (uint32_t)r), hnew,
                             mapa_u32(mbw, (uint32_t)r));
        }

        // ys write (off the signaling path)
        if (writeAll || t == T - 1)
            xp[((size_t)(b0 + bout) * T + t) * HID + jg] = hnew;

        xcur = xnext;
    }
}

// ---------------- head: last = ys2[:,T-1,:]; silu(last@W1^T+b1)@W2^T+b2 ----------------
__global__ __launch_bounds__(256) void head_kernel(
    const float* __restrict__ ys, const float* __restrict__ W1,
    const float* __restrict__ b1, const float* __restrict__ W2,
    const float* __restrict__ b2, float* __restrict__ out)
{
    __shared__ float hrow[HID];
    __shared__ float z[1024];
    int b = blockIdx.x;
    int tid = threadIdx.x, w = tid >> 5, l = tid & 31;

    const float* src = ys + ((size_t)b * TT + (TT - 1)) * HID;
    for (int i = tid; i < HID; i += 256) hrow[i] = src[i];
    __syncthreads();

    for (int m = w; m < 1024; m += 8) {
        const float4* wr = (const float4*)(W1 + (size_t)m * HID);
        float a = 0.0f;
        #pragma unroll
        for (int i = 0; i < 4; i++) {
            float4 wv = wr[l + 32 * i];
            float4 hv = *(const float4*)&hrow[4 * (l + 32 * i)];
            a = fmaf(wv.x, hv.x, a); a = fmaf(wv.y, hv.y, a);
            a = fmaf(wv.z, hv.z, a); a = fmaf(wv.w, hv.w, a);
        }
        a += __shfl_xor_sync(0xffffffffu, a, 16);
        a += __shfl_xor_sync(0xffffffffu, a, 8);
        a += __shfl_xor_sync(0xffffffffu, a, 4);
        a += __shfl_xor_sync(0xffffffffu, a, 2);
        a += __shfl_xor_sync(0xffffffffu, a, 1);
        if (l == 0) {
            float zz = a + b1[m];
            z[m] = zz / (1.0f + __expf(-zz));   // silu
        }
    }
    __syncthreads();

    {
        const float4* wr = (const float4*)(W2 + (size_t)w * 1024);
        float a = 0.0f;
        #pragma unroll
        for (int i = 0; i < 8; i++) {
            float4 wv = wr[l + 32 * i];
            float4 zv = *(const float4*)&z[4 * (l + 32 * i)];
            a = fmaf(wv.x, zv.x, a); a = fmaf(wv.y, zv.y, a);
            a = fmaf(wv.z, zv.z, a); a = fmaf(wv.w, zv.w, a);
        }
        a += __shfl_xor_sync(0xffffffffu, a, 16);
        a += __shfl_xor_sync(0xffffffffu, a, 8);
        a += __shfl_xor_sync(0xffffffffu, a, 4);
        a += __shfl_xor_sync(0xffffffffu, a, 2);
        a += __shfl_xor_sync(0xffffffffu, a, 1);
        if (l == 0) out[b * 8 + w] = a + b2[w];
    }
}

// ---------------- launch ----------------
extern "C" void kernel_launch(void* const* d_in, const int* in_sizes, int n_in,
                              void* d_out, int out_size) {
    const float* x     = (const float*)d_in[0];
    const float* Wih0  = (const float*)d_in[1];
    const float* Whh0  = (const float*)d_in[2];
    const float* bih0  = (const float*)d_in[3];
    const float* bhh0  = (const float*)d_in[4];
    const float* Wih1  = (const float*)d_in[5];
    const float* Whh1  = (const float*)d_in[6];
    const float* bih1  = (const float*)d_in[7];
    const float* bhh1  = (const float*)d_in[8];
    const float* Wih2  = (const float*)d_in[9];
    const float* Whh2  = (const float*)d_in[10];
    const float* bih2  = (const float*)d_in[11];
    const float* bhh2  = (const float*)d_in[12];
    const float* W1    = (const float*)d_in[13];
    const float* b1    = (const float*)d_in[14];
    const float* W2    = (const float*)d_in[15];
    const float* b2    = (const float*)d_in[16];
    float* out = (float*)d_out;

    float* bufA; cudaGetSymbolAddress((void**)&bufA, g_bufA);
    float* bufB; cudaGetSymbolAddress((void**)&bufB, g_bufB);

    // layer 0: xp0 then recurrence in place
    xp0_kernel<<<RTOT / 32, 256>>>(x, Wih0, bih0, bhh0, bufA);
    rnn_kernel<<<128, 512>>>(bufA, Whh0, TT, 1);

    // layer 1
    sgemm_kernel<<<dim3(HID / GBN, RTOT / GBM), 256>>>(bufA, Wih1, bih1, bhh1, bufB);
    rnn_kernel<<<128, 512>>>(bufB, Whh1, TT, 1);

    // layer 2 (only the last timestep of ys is consumed by the head)
    sgemm_kernel<<<dim3(HID / GBN, RTOT / GBM), 256>>>(bufB, Wih2, bih2, bhh2, bufA);
    rnn_kernel<<<128, 512>>>(bufA, Whh2, TT, 0);

    // head
    head_kernel<<<NB, 256>>>(bufA, W1, b1, W2, b2, out);
}